// round 9
// baseline (speedup 1.0000x reference)
#include <cuda_runtime.h>
#include <cuda_bf16.h>

#define NP 512

typedef unsigned long long u64;

// ---- packed f32x2 helpers (SASS FFMA2/FADD2/FMUL2 — only reachable via PTX) ----
__device__ __forceinline__ u64 pk2(float lo, float hi) {
    u64 r; asm("mov.b64 %0,{%1,%2};" : "=l"(r) : "f"(lo), "f"(hi)); return r;
}
__device__ __forceinline__ u64 fma2(u64 a, u64 b, u64 c) {
    u64 d; asm("fma.rn.f32x2 %0,%1,%2,%3;" : "=l"(d) : "l"(a), "l"(b), "l"(c)); return d;
}
__device__ __forceinline__ u64 add2(u64 a, u64 b) {
    u64 d; asm("add.rn.f32x2 %0,%1,%2;" : "=l"(d) : "l"(a), "l"(b)); return d;
}
__device__ __forceinline__ u64 mul2(u64 a, u64 b) {
    u64 d; asm("mul.rn.f32x2 %0,%1,%2;" : "=l"(d) : "l"(a), "l"(b)); return d;
}
// sign-flip both packed lanes on the ALU pipe (keeps fma pipe free)
__device__ __forceinline__ u64 neg2(u64 a) { return a ^ 0x8000000080000000ULL; }
// MUFU.RCP on both packed halves (mufu pipe, ~1ulp)
__device__ __forceinline__ u64 rcp2(u64 s) {
    float lo, hi, rl, rh;
    asm("mov.b64 {%0,%1}, %2;" : "=f"(lo), "=f"(hi) : "l"(s));
    asm("rcp.approx.f32 %0, %1;" : "=f"(rl) : "f"(lo));
    asm("rcp.approx.f32 %0, %1;" : "=f"(rh) : "f"(hi));
    u64 r; asm("mov.b64 %0,{%1,%2};" : "=l"(r) : "f"(rl), "f"(rh));
    return r;
}

// One block per batch element; 512 threads.
// Lane-packing over PARTICLES: smem u64 px[p] = (x[p], x[(p+256)&511]).
// LOAD REUSE (j-tiling): thread t (i = t&255, h = t>>8) owns TWO packed
// entries q1 = p[i] and q2 = p[i+128]. For each load j = i + k with
// k in [129+64h, 192+64h], the SAME px/py/pz[j] triple feeds:
//   q1-unit: pair offset k        (129..256 across h)
//   q2-unit: pair offset k - 128  (1..128 across h)
// Entry-coverage: q1 over entries 0..255, q2 over entries 128..383; both are
// complete single covers of all 512 particles (entry e and e+256 hold the
// same particle pair). Offsets 1..255 hit every unordered pair once; k=256
// (h=1 last unit, q1 side) double-counts distance-256 pairs -> weight 1/2.
// Total LJ = 2 * sum. LDS per packed unit: 1.5 LDS.64 (halved vs R5).
__global__ __launch_bounds__(NP, 1)
void lj_osc_kernel(const float* __restrict__ x, float* __restrict__ out) {
    __shared__ __align__(16) u64 px[NP];
    __shared__ __align__(16) u64 py[NP];
    __shared__ __align__(16) u64 pz[NP];
    __shared__ float red[5][16];

    const int b = blockIdx.x;
    const int t = threadIdx.x;
    const int i = t & 255;
    const int h = t >> 8;
    const float* __restrict__ xb = x + (size_t)b * (NP * 3);

    // Coalesced load of 1536 floats; scatter into packed u64 SoA arrays.
    // x[p] goes to lane0 of entry p and lane1 of entry (p+256)&511.
    {
        float v0 = xb[t];
        float v1 = xb[t + 512];
        float v2 = xb[t + 1024];
        int e, p, d;
#define SCATTER(VAL, EE) {                                              \
        e = (EE); p = e / 3; d = e - 3 * p;                             \
        u64* arr = (d == 0) ? px : (d == 1) ? py : pz;                  \
        float* f = (float*)arr;                                         \
        f[2 * p] = VAL;                                                 \
        f[2 * ((p + 256) & 511) + 1] = VAL; }
        SCATTER(v0, t)
        SCATTER(v1, t + 512)
        SCATTER(v2, t + 1024)
#undef SCATTER
    }
    __syncthreads();

    // Own packed coords: q1 = entry i, q2 = entry i+128; negated once.
    const u64 qx = px[i];
    const u64 qy = py[i];
    const u64 qz = pz[i];
    const u64 nx1 = neg2(qx);
    const u64 ny1 = neg2(qy);
    const u64 nz1 = neg2(qz);
    const u64 nx2 = neg2(px[i + 128]);
    const u64 ny2 = neg2(py[i + 128]);
    const u64 nz2 = neg2(pz[i + 128]);

    const u64 EPS  = pk2(1e-6f, 1e-6f);
    const u64 NEG2 = pk2(-2.0f, -2.0f);

    u64 a0 = 0, a1 = 0, b0 = 0, b1 = 0;

// One load triple at offset K feeding two packed units (q1 & q2).
#define UNIT2(ACC1, ACC2, K) {                                           \
        int j = i + (K);                                                 \
        u64 xj = px[j];                                                  \
        u64 yj = py[j];                                                  \
        u64 zj = pz[j];                                                  \
        {   u64 dx = add2(xj, nx1);                                      \
            u64 dy = add2(yj, ny1);                                      \
            u64 dz = add2(zj, nz1);                                      \
            u64 s  = fma2(dx, dx, fma2(dy, dy, fma2(dz, dz, EPS)));      \
            u64 yv = rcp2(s);                                            \
            u64 i6 = mul2(mul2(yv, yv), yv);                             \
            ACC1 = fma2(i6, add2(i6, NEG2), ACC1); }                     \
        {   u64 dx = add2(xj, nx2);                                      \
            u64 dy = add2(yj, ny2);                                      \
            u64 dz = add2(zj, nz2);                                      \
            u64 s  = fma2(dx, dx, fma2(dy, dy, fma2(dz, dz, EPS)));      \
            u64 yv = rcp2(s);                                            \
            u64 i6 = mul2(mul2(yv, yv), yv);                             \
            ACC2 = fma2(i6, add2(i6, NEG2), ACC2); } }

    const int ks = 129 + (h << 6);   // 129 (h=0) or 193 (h=1)

    // Two interleaved load streams (each feeds 2 independent accumulators).
    for (int m = 0; m < 31; ++m) {
        UNIT2(a0, b0, ks + m);
        UNIT2(a1, b1, ks + 32 + m);
    }
    UNIT2(a0, b0, ks + 31);
    // Last unit of stream 2: k = ks+63 (=192 for h=0, =256 for h=1).
    // For h=1 the q1 side is offset 256 -> weight 1/2; q2 side (offset 128)
    // stays weight 1.
    {
        int j = i + ks + 63;
        u64 xj = px[j];
        u64 yj = py[j];
        u64 zj = pz[j];
        {   u64 dx = add2(xj, nx1);
            u64 dy = add2(yj, ny1);
            u64 dz = add2(zj, nz1);
            u64 s  = fma2(dx, dx, fma2(dy, dy, fma2(dz, dz, EPS)));
            u64 yv = rcp2(s);
            u64 i6 = mul2(mul2(yv, yv), yv);
            u64 term = mul2(i6, add2(i6, NEG2));
            float w = h ? 0.5f : 1.0f;
            a1 = fma2(term, pk2(w, w), a1); }
        {   u64 dx = add2(xj, nx2);
            u64 dy = add2(yj, ny2);
            u64 dz = add2(zj, nz2);
            u64 s  = fma2(dx, dx, fma2(dy, dy, fma2(dz, dz, EPS)));
            u64 yv = rcp2(s);
            u64 i6 = mul2(mul2(yv, yv), yv);
            b1 = fma2(i6, add2(i6, NEG2), b1); }
    }
#undef UNIT2

    u64 accp = add2(add2(a0, a1), add2(b0, b1));
    float al, ah;
    asm("mov.b64 {%0,%1}, %2;" : "=f"(al), "=f"(ah) : "l"(accp));
    float acc = al + ah;

    // Oscillator terms: only h=0 threads contribute q1 lanes (each particle once).
    float sx = 0.f, sy = 0.f, sz = 0.f, ssq = 0.f;
    if (h == 0) {
        float xlo, xhi, ylo, yhi, zlo, zhi;
        asm("mov.b64 {%0,%1}, %2;" : "=f"(xlo), "=f"(xhi) : "l"(qx));
        asm("mov.b64 {%0,%1}, %2;" : "=f"(ylo), "=f"(yhi) : "l"(qy));
        asm("mov.b64 {%0,%1}, %2;" : "=f"(zlo), "=f"(zhi) : "l"(qz));
        sx = xlo + xhi;
        sy = ylo + yhi;
        sz = zlo + zhi;
        ssq = fmaf(xlo, xlo, fmaf(ylo, ylo, zlo * zlo))
            + fmaf(xhi, xhi, fmaf(yhi, yhi, zhi * zhi));
    }

    // Block reduction of 5 values: acc(LJ), sum_x, sum_y, sum_z, sum_sq
    float v[5] = {acc, sx, sy, sz, ssq};
    const unsigned FULL = 0xFFFFFFFFu;
    #pragma unroll
    for (int q = 0; q < 5; ++q) {
        float r = v[q];
        r += __shfl_down_sync(FULL, r, 16);
        r += __shfl_down_sync(FULL, r, 8);
        r += __shfl_down_sync(FULL, r, 4);
        r += __shfl_down_sync(FULL, r, 2);
        r += __shfl_down_sync(FULL, r, 1);
        v[q] = r;
    }
    const int warp = t >> 5;
    const int lane = t & 31;
    if (lane == 0) {
        #pragma unroll
        for (int q = 0; q < 5; ++q) red[q][warp] = v[q];
    }
    __syncthreads();
    if (warp == 0) {
        float r[5];
        #pragma unroll
        for (int q = 0; q < 5; ++q) {
            float val = (lane < 16) ? red[q][lane] : 0.0f;
            val += __shfl_down_sync(FULL, val, 8);
            val += __shfl_down_sync(FULL, val, 4);
            val += __shfl_down_sync(FULL, val, 2);
            val += __shfl_down_sync(FULL, val, 1);
            r[q] = val;
        }
        if (lane == 0) {
            float lj_total = 2.0f * r[0];
            float mean_sq = (r[1] * r[1] + r[2] * r[2] + r[3] * r[3]) * (1.0f / NP);
            float osc = 0.5f * (r[4] - mean_sq);
            out[b] = lj_total + osc;
        }
    }
}

extern "C" void kernel_launch(void* const* d_in, const int* in_sizes, int n_in,
                              void* d_out, int out_size) {
    const float* x = (const float*)d_in[0];
    float* out = (float*)d_out;
    int batches = in_sizes[0] / (NP * 3);   // 128
    lj_osc_kernel<<<batches, NP>>>(x, out);
}

// round 10
// speedup vs baseline: 1.0194x; 1.0194x over previous
#include <cuda_runtime.h>
#include <cuda_bf16.h>

#define NP 512

typedef unsigned long long u64;

// ---- packed f32x2 helpers ----
__device__ __forceinline__ u64 pk2(float lo, float hi) {
    u64 r; asm("mov.b64 %0,{%1,%2};" : "=l"(r) : "f"(lo), "f"(hi)); return r;
}
__device__ __forceinline__ u64 fma2(u64 a, u64 b, u64 c) {
    u64 d; asm("fma.rn.f32x2 %0,%1,%2,%3;" : "=l"(d) : "l"(a), "l"(b), "l"(c)); return d;
}
__device__ __forceinline__ u64 add2(u64 a, u64 b) {
    u64 d; asm("add.rn.f32x2 %0,%1,%2;" : "=l"(d) : "l"(a), "l"(b)); return d;
}
__device__ __forceinline__ u64 neg2(u64 a) { return a ^ 0x8000000080000000ULL; }
// scalar MUFU reciprocal (~1ulp)
__device__ __forceinline__ float frcp(float x) {
    float r; asm("rcp.approx.f32 %0,%1;" : "=f"(r) : "f"(x)); return r;
}

// One block per batch element; 512 threads.
// Lane-packing over PARTICLES: smem u64 px[p] = (x[p], x[(p+256)&511]).
// LOAD REUSE: thread t (i = t&255, h = t>>8) owns q1 = p[i], q2 = p[i+128].
// Each load j = i + k (k in [129+64h, 192+64h]) feeds pair offsets k (q1)
// and k-128 (q2). Offsets 1..255 cover every unordered pair once; k=256
// (h=1, q1 side of last unit) double-counts -> weight 1/2. Total = 2*sum.
//
// Front-end packed (6 f32x2: 3 add2 + 3 fma2 -> s). Back-end SCALAR:
// unpack s (register aliasing), per lane MUFU.RCP -> cube (2 FMUL) ->
// Sum_i6 (FADD) + Sum_i12 (FFMA). lj = Sum_i12 - 2*Sum_i6 at the end.
// No pack/unpack MOV traffic around MUFU (the R8/R9 alu parasite).
__global__ __launch_bounds__(NP, 1)
void lj_osc_kernel(const float* __restrict__ x, float* __restrict__ out) {
    __shared__ __align__(16) u64 px[NP];
    __shared__ __align__(16) u64 py[NP];
    __shared__ __align__(16) u64 pz[NP];
    __shared__ float red[5][16];

    const int b = blockIdx.x;
    const int t = threadIdx.x;
    const int i = t & 255;
    const int h = t >> 8;
    const float* __restrict__ xb = x + (size_t)b * (NP * 3);

    // Coalesced load of 1536 floats; scatter into packed u64 SoA arrays.
    // x[p] -> lane0 of entry p, lane1 of entry (p+256)&511.
    {
        float v0 = xb[t];
        float v1 = xb[t + 512];
        float v2 = xb[t + 1024];
        int e, p, d;
#define SCATTER(VAL, EE) {                                              \
        e = (EE); p = e / 3; d = e - 3 * p;                             \
        u64* arr = (d == 0) ? px : (d == 1) ? py : pz;                  \
        float* f = (float*)arr;                                         \
        f[2 * p] = VAL;                                                 \
        f[2 * ((p + 256) & 511) + 1] = VAL; }
        SCATTER(v0, t)
        SCATTER(v1, t + 512)
        SCATTER(v2, t + 1024)
#undef SCATTER
    }
    __syncthreads();

    const u64 qx = px[i];
    const u64 qy = py[i];
    const u64 qz = pz[i];
    const u64 nx1 = neg2(qx);
    const u64 ny1 = neg2(qy);
    const u64 nz1 = neg2(qz);
    const u64 nx2 = neg2(px[i + 128]);
    const u64 ny2 = neg2(py[i + 128]);
    const u64 nz2 = neg2(pz[i + 128]);

    const u64 EPS = pk2(1e-6f, 1e-6f);

    // Scalar accumulators: 4x (Sum_i6, Sum_i12) for ILP.
    float a6_0 = 0.f, a12_0 = 0.f, a6_1 = 0.f, a12_1 = 0.f;
    float b6_0 = 0.f, b12_0 = 0.f, b6_1 = 0.f, b12_1 = 0.f;
    float tacc = 0.f;   // weighted tail terms

// packed front: distance^2 for one q against loaded j-triple
#define FRONT(SOUT, XJ, YJ, ZJ, NX, NY, NZ) {                            \
        u64 dx = add2(XJ, NX);                                           \
        u64 dy = add2(YJ, NY);                                           \
        u64 dz = add2(ZJ, NZ);                                           \
        SOUT = fma2(dx, dx, fma2(dy, dy, fma2(dz, dz, EPS))); }

// scalar back-end: both lanes of S into (A6L,A12L)/(A6H,A12H)
#define BACKEND(S, A6L, A12L, A6H, A12H) {                               \
        float lo, hi;                                                    \
        asm("mov.b64 {%0,%1}, %2;" : "=f"(lo), "=f"(hi) : "l"(S));       \
        float rl = frcp(lo), rh = frcp(hi);                              \
        float l3 = rl * rl * rl;                                         \
        float h3 = rh * rh * rh;                                         \
        A6L += l3;  A12L = fmaf(l3, l3, A12L);                           \
        A6H += h3;  A12H = fmaf(h3, h3, A12H); }

// one load triple feeding q1-unit and q2-unit
#define UNIT2(K) {                                                       \
        int j = i + (K);                                                 \
        u64 xj = px[j];                                                  \
        u64 yj = py[j];                                                  \
        u64 zj = pz[j];                                                  \
        u64 s1, s2;                                                      \
        FRONT(s1, xj, yj, zj, nx1, ny1, nz1)                             \
        FRONT(s2, xj, yj, zj, nx2, ny2, nz2)                             \
        BACKEND(s1, a6_0, a12_0, a6_1, a12_1)                            \
        BACKEND(s2, b6_0, b12_0, b6_1, b12_1) }

    const int ks = 129 + (h << 6);   // 129 (h=0) or 193 (h=1)

    for (int m = 0; m < 31; ++m) {
        UNIT2(ks + m);
        UNIT2(ks + 32 + m);
    }
    UNIT2(ks + 31);
    // Tail: k = ks+63 (=192 for h=0, =256 for h=1). q1 side gets weight
    // 1/2 when h=1 (offset 256 double-counted); q2 side (offset 64/128)
    // stays weight 1.
    {
        int j = i + ks + 63;
        u64 xj = px[j];
        u64 yj = py[j];
        u64 zj = pz[j];
        u64 s1, s2;
        FRONT(s1, xj, yj, zj, nx1, ny1, nz1)
        FRONT(s2, xj, yj, zj, nx2, ny2, nz2)
        {   // q1 side with weight
            float lo, hi;
            asm("mov.b64 {%0,%1}, %2;" : "=f"(lo), "=f"(hi) : "l"(s1));
            float rl = frcp(lo), rh = frcp(hi);
            float l3 = rl * rl * rl;
            float h3 = rh * rh * rh;
            float w = h ? 0.5f : 1.0f;
            tacc += w * (fmaf(l3, l3 - 2.0f, 0.f) + fmaf(h3, h3 - 2.0f, 0.f));
        }
        BACKEND(s2, b6_0, b12_0, b6_1, b12_1)
    }
#undef UNIT2
#undef BACKEND
#undef FRONT

    float sum6  = (a6_0 + a6_1) + (b6_0 + b6_1);
    float sum12 = (a12_0 + a12_1) + (b12_0 + b12_1);
    float acc = fmaf(-2.0f, sum6, sum12) + tacc;

    // Oscillator terms: only h=0 threads contribute (each particle once).
    float sx = 0.f, sy = 0.f, sz = 0.f, ssq = 0.f;
    if (h == 0) {
        float xlo, xhi, ylo, yhi, zlo, zhi;
        asm("mov.b64 {%0,%1}, %2;" : "=f"(xlo), "=f"(xhi) : "l"(qx));
        asm("mov.b64 {%0,%1}, %2;" : "=f"(ylo), "=f"(yhi) : "l"(qy));
        asm("mov.b64 {%0,%1}, %2;" : "=f"(zlo), "=f"(zhi) : "l"(qz));
        sx = xlo + xhi;
        sy = ylo + yhi;
        sz = zlo + zhi;
        ssq = fmaf(xlo, xlo, fmaf(ylo, ylo, zlo * zlo))
            + fmaf(xhi, xhi, fmaf(yhi, yhi, zhi * zhi));
    }

    // Block reduction of 5 values: acc(LJ), sum_x, sum_y, sum_z, sum_sq
    float v[5] = {acc, sx, sy, sz, ssq};
    const unsigned FULL = 0xFFFFFFFFu;
    #pragma unroll
    for (int q = 0; q < 5; ++q) {
        float r = v[q];
        r += __shfl_down_sync(FULL, r, 16);
        r += __shfl_down_sync(FULL, r, 8);
        r += __shfl_down_sync(FULL, r, 4);
        r += __shfl_down_sync(FULL, r, 2);
        r += __shfl_down_sync(FULL, r, 1);
        v[q] = r;
    }
    const int warp = t >> 5;
    const int lane = t & 31;
    if (lane == 0) {
        #pragma unroll
        for (int q = 0; q < 5; ++q) red[q][warp] = v[q];
    }
    __syncthreads();
    if (warp == 0) {
        float r[5];
        #pragma unroll
        for (int q = 0; q < 5; ++q) {
            float val = (lane < 16) ? red[q][lane] : 0.0f;
            val += __shfl_down_sync(FULL, val, 8);
            val += __shfl_down_sync(FULL, val, 4);
            val += __shfl_down_sync(FULL, val, 2);
            val += __shfl_down_sync(FULL, val, 1);
            r[q] = val;
        }
        if (lane == 0) {
            float lj_total = 2.0f * r[0];
            float mean_sq = (r[1] * r[1] + r[2] * r[2] + r[3] * r[3]) * (1.0f / NP);
            float osc = 0.5f * (r[4] - mean_sq);
            out[b] = lj_total + osc;
        }
    }
}

extern "C" void kernel_launch(void* const* d_in, const int* in_sizes, int n_in,
                              void* d_out, int out_size) {
    const float* x = (const float*)d_in[0];
    float* out = (float*)d_out;
    int batches = in_sizes[0] / (NP * 3);   // 128
    lj_osc_kernel<<<batches, NP>>>(x, out);
}